// round 9
// baseline (speedup 1.0000x reference)
#include <cuda_runtime.h>
#include <cuda_fp16.h>
#include <mma.h>
#include <math.h>

using namespace nvcuda;

#define N_NODES 50000
#define N_PAD   50048              // 782 * 64
#define D_IN    128
#define D_H     128
#define D_Z     64
#define E_EDGES 800000

// ---- scratch (device globals; zero-initialized at module load) ----
__device__ int   g_cnt      [N_NODES];       // re-zeroed by k_bigscan each run
__device__ int   g_cursor   [N_NODES];       // re-zeroed by k_agg<1> each run
__device__ int   g_row_start[N_NODES + 1];
__device__ int   g_csr_src  [E_EDGES];
__device__ float g_dinv     [N_NODES];
__device__ __align__(16) __half g_xw  [N_NODES * D_H];  // (X@W1) * dinv[row]
__device__ __align__(16) __half g_h   [N_NODES * D_H];  // hidden * dinv[row]
__device__ __align__(16) __half g_aggh[(size_t)N_PAD * D_H]; // A_norm@hidden (padded rows stay 0)

// ---------------------------------------------------------------------------
// degree count
// ---------------------------------------------------------------------------
__global__ void k_count(const int* __restrict__ dst) {
    int e = blockIdx.x * blockDim.x + threadIdx.x;
    if (e < E_EDGES) {
        int d = dst[e];
        if ((unsigned)d < N_NODES) atomicAdd(&g_cnt[d], 1);
    }
}

// ---------------------------------------------------------------------------
// single-block scan over all 50K degrees:
//   g_row_start = exclusive prefix of cnt ; dinv = rsqrt(cnt+1) ; cnt = 0
// 1024 threads, 49 contiguous elements each (1024*49 = 50176 >= 50000).
// ---------------------------------------------------------------------------
#define SEG 49
__global__ void k_bigscan() {
    __shared__ int sh[1024];
    const int t    = threadIdx.x;
    const int base = t * SEG;

    int sum = 0;
    #pragma unroll
    for (int k = 0; k < SEG; ++k) {
        int i = base + k;
        if (i < N_NODES) sum += g_cnt[i];
    }
    sh[t] = sum;
    __syncthreads();
    #pragma unroll
    for (int off = 1; off < 1024; off <<= 1) {
        int add = (t >= off) ? sh[t - off] : 0;
        __syncthreads();
        sh[t] += add;
        __syncthreads();
    }
    int run = sh[t] - sum;   // exclusive prefix of this segment
    #pragma unroll
    for (int k = 0; k < SEG; ++k) {
        int i = base + k;
        if (i < N_NODES) {
            int c = g_cnt[i];
            g_row_start[i] = run;
            run += c;
            g_dinv[i] = rsqrtf((float)(c + 1));  // +1 self-loop
            g_cnt[i] = 0;                        // reset for next replay
        }
    }
    if (t == 1023) g_row_start[N_NODES] = sh[1023];
}

__global__ void k_scatter(const int* __restrict__ src,
                          const int* __restrict__ dst) {
    int e = blockIdx.x * blockDim.x + threadIdx.x;
    if (e >= E_EDGES) return;
    int d = dst[e];
    int s = src[e];
    if ((unsigned)d >= N_NODES || (unsigned)s >= N_NODES) return;
    int pos = g_row_start[d] + atomicAdd(&g_cursor[d], 1);
    g_csr_src[pos] = s;
}

// ---------------------------------------------------------------------------
// GEMM1 (tensor cores): g_xw = fp16( (x @ W1) * dinv[row] )
// 256 threads = 8 warps (4 row-tiles x 2 col-tiles), 64 rows/block.
// B staged from f32 W1 directly (convert while staging).
// ---------------------------------------------------------------------------
__global__ void k_gemm1(const float* __restrict__ x,
                        const float* __restrict__ W1) {
    __shared__ __align__(16) char smraw[49152];
    __half* Ah = (__half*)smraw;              // 64x128 fp16 = 16 KB
    __half* Bh = (__half*)(smraw + 16384);    // 128x128 fp16 = 32 KB
    float*  Cs = (float*)smraw;               // 64x128 f32 = 32 KB (overlays after mainloop)

    const int tid  = threadIdx.x;
    const int row0 = blockIdx.x * 64;

    // stage A: f32 -> f16 (zero-pad OOB rows)
    for (int i = tid; i < 64 * 32; i += 256) {
        int r = i >> 5, c4 = i & 31;
        int rg = row0 + r;
        float4 v = make_float4(0.f, 0.f, 0.f, 0.f);
        if (rg < N_NODES) v = ((const float4*)(x + (size_t)rg * D_IN))[c4];
        __half2 h0 = __floats2half2_rn(v.x, v.y);
        __half2 h1 = __floats2half2_rn(v.z, v.w);
        uint2 u;
        u.x = *reinterpret_cast<unsigned*>(&h0);
        u.y = *reinterpret_cast<unsigned*>(&h1);
        ((uint2*)Ah)[i] = u;
    }
    // stage B: f32 -> f16
    for (int i = tid; i < 128 * 32; i += 256) {
        float4 v = ((const float4*)W1)[i];
        __half2 h0 = __floats2half2_rn(v.x, v.y);
        __half2 h1 = __floats2half2_rn(v.z, v.w);
        uint2 u;
        u.x = *reinterpret_cast<unsigned*>(&h0);
        u.y = *reinterpret_cast<unsigned*>(&h1);
        ((uint2*)Bh)[i] = u;
    }
    __syncthreads();

    const int wid = tid >> 5, wr = wid & 3, wc = wid >> 2;

    wmma::fragment<wmma::accumulator, 16, 16, 16, float> fc[4];
    #pragma unroll
    for (int c = 0; c < 4; ++c) wmma::fill_fragment(fc[c], 0.0f);

    #pragma unroll
    for (int k = 0; k < 8; ++k) {
        wmma::fragment<wmma::matrix_a, 16, 16, 16, __half, wmma::row_major> fa;
        wmma::load_matrix_sync(fa, Ah + (wr * 16) * 128 + k * 16, 128);
        #pragma unroll
        for (int c = 0; c < 4; ++c) {
            wmma::fragment<wmma::matrix_b, 16, 16, 16, __half, wmma::row_major> fb;
            wmma::load_matrix_sync(fb, Bh + (k * 16) * 128 + wc * 64 + c * 16, 128);
            wmma::mma_sync(fc[c], fa, fb, fc[c]);
        }
    }
    __syncthreads();

    #pragma unroll
    for (int c = 0; c < 4; ++c)
        wmma::store_matrix_sync(Cs + (wr * 16) * 128 + wc * 64 + c * 16, fc[c],
                                128, wmma::mem_row_major);
    __syncthreads();

    // epilogue: scale by dinv[row], convert to fp16
    for (int i = tid; i < 64 * 32; i += 256) {
        int r = i >> 5, c4 = i & 31;
        int rg = row0 + r;
        if (rg >= N_NODES) continue;
        float di = g_dinv[rg];
        float4 v = ((const float4*)(Cs + r * 128))[c4];
        __half2 h0 = __floats2half2_rn(v.x * di, v.y * di);
        __half2 h1 = __floats2half2_rn(v.z * di, v.w * di);
        uint2 u;
        u.x = *reinterpret_cast<unsigned*>(&h0);
        u.y = *reinterpret_cast<unsigned*>(&h1);
        ((uint2*)(g_xw + (size_t)rg * D_H))[c4] = u;
    }
}

// ---------------------------------------------------------------------------
// gather-aggregate: 16 lanes per node (2 nodes/warp), uint4 = 8 halves/lane.
// Pre-scaled tables: acc = table[node] + sum_s table[s]; result = acc*dinv[node]
// LAYER==1: h = relu(result + b); store fp16(h * dinv) -> g_h ; zero cursor
// LAYER==2: store fp16(result) -> g_aggh
// ---------------------------------------------------------------------------
__device__ __forceinline__ void h8_add(float4& a, float4& b, uint4 u) {
    __half2 p0 = *reinterpret_cast<__half2*>(&u.x);
    __half2 p1 = *reinterpret_cast<__half2*>(&u.y);
    __half2 p2 = *reinterpret_cast<__half2*>(&u.z);
    __half2 p3 = *reinterpret_cast<__half2*>(&u.w);
    float2 f0 = __half22float2(p0);
    float2 f1 = __half22float2(p1);
    float2 f2 = __half22float2(p2);
    float2 f3 = __half22float2(p3);
    a.x += f0.x; a.y += f0.y; a.z += f1.x; a.w += f1.y;
    b.x += f2.x; b.y += f2.y; b.z += f3.x; b.w += f3.y;
}

template <int LAYER>
__global__ void k_agg(const float* __restrict__ bias) {
    const __half* table = (LAYER == 1) ? g_xw : g_h;

    int gtid = blockIdx.x * blockDim.x + threadIdx.x;
    int node = gtid >> 4;
    int lane = gtid & 15;          // 16 lanes/node, 8 halves each
    if (node >= N_NODES) return;

    const int start = g_row_start[node];
    const int end   = g_row_start[node + 1];
    const float dd  = g_dinv[node];

    float4 a0 = make_float4(0.f, 0.f, 0.f, 0.f);
    float4 a1 = make_float4(0.f, 0.f, 0.f, 0.f);
    h8_add(a0, a1, __ldg((const uint4*)(table + (size_t)node * D_H) + lane));  // self

    int i = start;
    for (; i + 2 <= end; i += 2) {
        int s0 = g_csr_src[i + 0];
        int s1 = g_csr_src[i + 1];
        uint4 u0 = __ldg((const uint4*)(table + (size_t)s0 * D_H) + lane);
        uint4 u1 = __ldg((const uint4*)(table + (size_t)s1 * D_H) + lane);
        h8_add(a0, a1, u0);
        h8_add(a0, a1, u1);
    }
    if (i < end) {
        int s = g_csr_src[i];
        h8_add(a0, a1, __ldg((const uint4*)(table + (size_t)s * D_H) + lane));
    }

    a0.x *= dd; a0.y *= dd; a0.z *= dd; a0.w *= dd;
    a1.x *= dd; a1.y *= dd; a1.z *= dd; a1.w *= dd;

    uint4 o;
    if (LAYER == 1) {
        float4 b0 = ((const float4*)bias)[2 * lane];
        float4 b1 = ((const float4*)bias)[2 * lane + 1];
        float h0 = fmaxf(a0.x + b0.x, 0.0f) * dd;
        float h1 = fmaxf(a0.y + b0.y, 0.0f) * dd;
        float h2 = fmaxf(a0.z + b0.z, 0.0f) * dd;
        float h3 = fmaxf(a0.w + b0.w, 0.0f) * dd;
        float h4 = fmaxf(a1.x + b1.x, 0.0f) * dd;
        float h5 = fmaxf(a1.y + b1.y, 0.0f) * dd;
        float h6 = fmaxf(a1.z + b1.z, 0.0f) * dd;
        float h7 = fmaxf(a1.w + b1.w, 0.0f) * dd;
        __half2 q0 = __floats2half2_rn(h0, h1);
        __half2 q1 = __floats2half2_rn(h2, h3);
        __half2 q2 = __floats2half2_rn(h4, h5);
        __half2 q3 = __floats2half2_rn(h6, h7);
        o.x = *reinterpret_cast<unsigned*>(&q0);
        o.y = *reinterpret_cast<unsigned*>(&q1);
        o.z = *reinterpret_cast<unsigned*>(&q2);
        o.w = *reinterpret_cast<unsigned*>(&q3);
        ((uint4*)(g_h + (size_t)node * D_H))[lane] = o;
        if (lane == 0) g_cursor[node] = 0;       // reset for next replay
    } else {
        __half2 q0 = __floats2half2_rn(a0.x, a0.y);
        __half2 q1 = __floats2half2_rn(a0.z, a0.w);
        __half2 q2 = __floats2half2_rn(a1.x, a1.y);
        __half2 q3 = __floats2half2_rn(a1.z, a1.w);
        o.x = *reinterpret_cast<unsigned*>(&q0);
        o.y = *reinterpret_cast<unsigned*>(&q1);
        o.z = *reinterpret_cast<unsigned*>(&q2);
        o.w = *reinterpret_cast<unsigned*>(&q3);
        ((uint4*)(g_aggh + (size_t)node * D_H))[lane] = o;
    }
}

// ---------------------------------------------------------------------------
// GEMM2 (tensor cores) + VGAE epilogue:
//   [mu | ls] = g_aggh @ [Wmu|Wls] ; z = mu+bmu + eps*exp(ls+bls)
// B staged from f32 Wmu/Wls directly. A frags from global fp16 (padded rows 0).
// ---------------------------------------------------------------------------
__global__ void k_gemm2(const float* __restrict__ Wmu,
                        const float* __restrict__ Wls,
                        const float* __restrict__ bmu,
                        const float* __restrict__ bls,
                        const float* __restrict__ eps,
                        float* __restrict__ out) {
    __shared__ __align__(16) char smraw[32768];
    __half* Bh = (__half*)smraw;             // 128x128 fp16 = 32 KB
    float*  Cs = (float*)smraw;              // 64x128 f32 = 32 KB (overlays B)

    const int tid  = threadIdx.x;
    const int row0 = blockIdx.x * 64;

    // stage B = [Wmu | Wls], f32 -> f16
    for (int i = tid; i < 2048; i += 256) {   // float4 over Wmu (128x64/4)
        int k = i >> 4, c4 = i & 15;
        float4 vm = ((const float4*)Wmu)[i];
        float4 vl = ((const float4*)Wls)[i];
        __half2 m0 = __floats2half2_rn(vm.x, vm.y);
        __half2 m1 = __floats2half2_rn(vm.z, vm.w);
        __half2 l0 = __floats2half2_rn(vl.x, vl.y);
        __half2 l1 = __floats2half2_rn(vl.z, vl.w);
        uint2 um, ul;
        um.x = *reinterpret_cast<unsigned*>(&m0);
        um.y = *reinterpret_cast<unsigned*>(&m1);
        ul.x = *reinterpret_cast<unsigned*>(&l0);
        ul.y = *reinterpret_cast<unsigned*>(&l1);
        ((uint2*)(Bh + k * 128))[c4]      = um;
        ((uint2*)(Bh + k * 128 + 64))[c4] = ul;
    }
    __syncthreads();

    const int wid = tid >> 5, wr = wid & 3, wc = wid >> 2;
    const __half* Ag = g_aggh + (size_t)(row0 + wr * 16) * D_H;

    wmma::fragment<wmma::accumulator, 16, 16, 16, float> fc[4];
    #pragma unroll
    for (int c = 0; c < 4; ++c) wmma::fill_fragment(fc[c], 0.0f);

    #pragma unroll
    for (int k = 0; k < 8; ++k) {
        wmma::fragment<wmma::matrix_a, 16, 16, 16, __half, wmma::row_major> fa;
        wmma::load_matrix_sync(fa, Ag + k * 16, 128);
        #pragma unroll
        for (int c = 0; c < 4; ++c) {
            wmma::fragment<wmma::matrix_b, 16, 16, 16, __half, wmma::row_major> fb;
            wmma::load_matrix_sync(fb, Bh + (k * 16) * 128 + wc * 64 + c * 16, 128);
            wmma::mma_sync(fc[c], fa, fb, fc[c]);
        }
    }
    __syncthreads();

    #pragma unroll
    for (int c = 0; c < 4; ++c)
        wmma::store_matrix_sync(Cs + (wr * 16) * 128 + wc * 64 + c * 16, fc[c],
                                128, wmma::mem_row_major);
    __syncthreads();

    const size_t seg = (size_t)N_NODES * D_Z;
    for (int i = tid; i < 64 * 64; i += 256) {
        int r = i >> 6, c = i & 63;
        int rg = row0 + r;
        if (rg >= N_NODES) continue;
        float mu = Cs[r * 128 + c]      + bmu[c];
        float ls = Cs[r * 128 + 64 + c] + bls[c];
        size_t off = (size_t)rg * D_Z + c;
        out[off]           = mu + eps[off] * expf(ls);
        out[seg + off]     = mu;
        out[2 * seg + off] = ls;
    }
}

// ---------------------------------------------------------------------------
extern "C" void kernel_launch(void* const* d_in, const int* in_sizes, int n_in,
                              void* d_out, int out_size) {
    const float* x   = (const float*)d_in[0];
    const int*   ei  = (const int*)d_in[1];     // [2, E] int32
    const float* eps = (const float*)d_in[2];
    const float* W1  = (const float*)d_in[3];
    const float* b1  = (const float*)d_in[4];
    const float* Wmu = (const float*)d_in[5];
    const float* bmu = (const float*)d_in[6];
    const float* Wls = (const float*)d_in[7];
    const float* bls = (const float*)d_in[8];
    float*       out = (float*)d_out;

    const int* src = ei;
    const int* dst = ei + E_EDGES;

    // CSR build (g_cnt / g_cursor arrive zeroed: load-time init + in-kernel reset)
    k_count  <<<(E_EDGES + 255) / 256, 256>>>(dst);
    k_bigscan<<<1, 1024>>>();
    k_scatter<<<(E_EDGES + 255) / 256, 256>>>(src, dst);

    // layer 1: tensor-core transform (pre-scaled fp16 table)
    k_gemm1<<<N_PAD / 64, 256>>>(x, W1);

    // aggregations (16 lanes/node, 2 nodes/warp)
    {
        long long total = (long long)N_NODES * 16;
        int blocks = (int)((total + 255) / 256);
        k_agg<1><<<blocks, 256>>>(b1);
        k_agg<2><<<blocks, 256>>>(nullptr);
    }

    // output tensor-core GEMM + reparameterization
    k_gemm2<<<N_PAD / 64, 256>>>(Wmu, Wls, bmu, bls, eps, out);
}

// round 10
// speedup vs baseline: 1.6427x; 1.6427x over previous
#include <cuda_runtime.h>
#include <cuda_fp16.h>
#include <mma.h>
#include <math.h>

using namespace nvcuda;

#define N_NODES 50000
#define N_PAD   50048              // 782 * 64
#define D_IN    128
#define D_H     128
#define D_Z     64
#define E_EDGES 800000

#define CHUNK   512
#define NCHUNKS ((N_NODES + CHUNK - 1) / CHUNK)   // 98

// ---- scratch (device globals; zero-init at load, re-zeroed in-kernel) ----
__device__ int   g_cnt      [N_NODES];       // reset by k_chunk_scan
__device__ int   g_cursor   [N_NODES];       // reset by k_agg<1>
__device__ int   g_row_start[N_NODES + 1];
__device__ int   g_chunk_sum[NCHUNKS];
__device__ int   g_chunk_off[NCHUNKS];
__device__ int   g_csr_src  [E_EDGES];
__device__ float g_dinv     [N_NODES];
__device__ __align__(16) __half g_w1h [D_IN * D_H];     // fp16 W1
__device__ __align__(16) __half g_w2h [D_H * 128];      // fp16 [Wmu | Wls]
__device__ __align__(16) __half g_xw  [N_NODES * D_H];  // (X@W1) * dinv[row]
__device__ __align__(16) __half g_h   [N_NODES * D_H];  // hidden * dinv[row]
__device__ __align__(16) __half g_aggh[(size_t)N_PAD * D_H]; // A_norm@hidden (padded rows stay 0)

// ---------------------------------------------------------------------------
// CSR build (R8 pipeline, k_init folded away)
// ---------------------------------------------------------------------------
__global__ void k_count(const int* __restrict__ dst) {
    int e = blockIdx.x * blockDim.x + threadIdx.x;
    if (e < E_EDGES) {
        int d = dst[e];
        if ((unsigned)d < N_NODES) atomicAdd(&g_cnt[d], 1);
    }
}

__global__ void k_chunk_sum() {
    __shared__ int sh[CHUNK];
    int t = threadIdx.x;
    int i = blockIdx.x * CHUNK + t;
    int v = (i < N_NODES) ? g_cnt[i] : 0;
    sh[t] = v;
    __syncthreads();
    for (int off = CHUNK / 2; off > 0; off >>= 1) {
        if (t < off) sh[t] += sh[t + off];
        __syncthreads();
    }
    if (t == 0) g_chunk_sum[blockIdx.x] = sh[0];
}

__global__ void k_scan_chunks() {
    __shared__ int sh[128];
    int t = threadIdx.x;
    int v = (t < NCHUNKS) ? g_chunk_sum[t] : 0;
    sh[t] = v;
    __syncthreads();
    #pragma unroll
    for (int off = 1; off < 128; off <<= 1) {
        int add = (t >= off) ? sh[t - off] : 0;
        __syncthreads();
        sh[t] += add;
        __syncthreads();
    }
    if (t < NCHUNKS) g_chunk_off[t] = sh[t] - v;
    if (t == 127)    g_row_start[N_NODES] = sh[127];
}

__global__ void k_chunk_scan() {
    __shared__ int sh[CHUNK];
    int t = threadIdx.x;
    int i = blockIdx.x * CHUNK + t;
    int v = (i < N_NODES) ? g_cnt[i] : 0;
    sh[t] = v;
    __syncthreads();
    for (int off = 1; off < CHUNK; off <<= 1) {
        int add = (t >= off) ? sh[t - off] : 0;
        __syncthreads();
        sh[t] += add;
        __syncthreads();
    }
    if (i < N_NODES) {
        g_row_start[i] = sh[t] - v + g_chunk_off[blockIdx.x];
        g_dinv[i] = rsqrtf((float)(v + 1));     // +1 self-loop
        g_cnt[i] = 0;                           // reset for next replay
    }
}

__global__ void k_scatter(const int* __restrict__ src,
                          const int* __restrict__ dst) {
    int e = blockIdx.x * blockDim.x + threadIdx.x;
    if (e >= E_EDGES) return;
    int d = dst[e];
    int s = src[e];
    if ((unsigned)d >= N_NODES || (unsigned)s >= N_NODES) return;
    int pos = g_row_start[d] + atomicAdd(&g_cursor[d], 1);
    g_csr_src[pos] = s;
}

// ---------------------------------------------------------------------------
// weight conversion: W1 -> g_w1h ; [Wmu|Wls] -> g_w2h
// ---------------------------------------------------------------------------
__global__ void k_cvt_w(const float* __restrict__ W1,
                        const float* __restrict__ Wmu,
                        const float* __restrict__ Wls) {
    int i = blockIdx.x * blockDim.x + threadIdx.x;  // 0..32767
    if (i < D_IN * D_H) {
        g_w1h[i] = __float2half(W1[i]);
    } else {
        int j = i - D_IN * D_H;
        int k = j >> 7, n = j & 127;
        float v = (n < 64) ? Wmu[k * 64 + n] : Wls[k * 64 + (n - 64)];
        g_w2h[j] = __float2half(v);
    }
}

// ---------------------------------------------------------------------------
// GEMM1 (tensor cores): g_xw = fp16( (x*dinv[row]) @ W1 )
// 256 threads = 8 warps (4 row-tiles x 2 col-tiles), 64 rows/block.
// A pre-scaled by dinv while staging; B read from GLOBAL fp16 (L2-hit);
// smem = 32 KB (A 16 KB, C 32 KB overlay) -> 7 CTAs/SM.
// ---------------------------------------------------------------------------
__global__ void k_gemm1(const float* __restrict__ x) {
    __shared__ __align__(16) char smraw[32768];
    __half* Ah = (__half*)smraw;              // 64x128 fp16 = 16 KB
    float*  Cs = (float*)smraw;               // 64x128 f32 = 32 KB (overlays A)

    const int tid  = threadIdx.x;
    const int row0 = blockIdx.x * 64;

    // stage A: f32 -> f16, pre-scaled by dinv[row] (zero-pad OOB rows)
    for (int i = tid; i < 64 * 32; i += 256) {
        int r = i >> 5, c4 = i & 31;
        int rg = row0 + r;
        float4 v = make_float4(0.f, 0.f, 0.f, 0.f);
        float di = 0.0f;
        if (rg < N_NODES) {
            v  = ((const float4*)(x + (size_t)rg * D_IN))[c4];
            di = g_dinv[rg];
        }
        __half2 h0 = __floats2half2_rn(v.x * di, v.y * di);
        __half2 h1 = __floats2half2_rn(v.z * di, v.w * di);
        uint2 u;
        u.x = *reinterpret_cast<unsigned*>(&h0);
        u.y = *reinterpret_cast<unsigned*>(&h1);
        ((uint2*)Ah)[i] = u;
    }
    __syncthreads();

    const int wid = tid >> 5, wr = wid & 3, wc = wid >> 2;

    wmma::fragment<wmma::accumulator, 16, 16, 16, float> fc[4];
    #pragma unroll
    for (int c = 0; c < 4; ++c) wmma::fill_fragment(fc[c], 0.0f);

    #pragma unroll
    for (int k = 0; k < 8; ++k) {
        wmma::fragment<wmma::matrix_a, 16, 16, 16, __half, wmma::row_major> fa;
        wmma::load_matrix_sync(fa, Ah + (wr * 16) * 128 + k * 16, 128);
        #pragma unroll
        for (int c = 0; c < 4; ++c) {
            wmma::fragment<wmma::matrix_b, 16, 16, 16, __half, wmma::row_major> fb;
            wmma::load_matrix_sync(fb, g_w1h + (k * 16) * 128 + wc * 64 + c * 16, 128);
            wmma::mma_sync(fc[c], fa, fb, fc[c]);
        }
    }
    __syncthreads();   // all A reads done before C overlays

    #pragma unroll
    for (int c = 0; c < 4; ++c)
        wmma::store_matrix_sync(Cs + (wr * 16) * 128 + wc * 64 + c * 16, fc[c],
                                128, wmma::mem_row_major);
    __syncthreads();

    // epilogue: convert to fp16 (already scaled)
    for (int i = tid; i < 64 * 32; i += 256) {
        int r = i >> 5, c4 = i & 31;
        int rg = row0 + r;
        if (rg >= N_NODES) continue;
        float4 v = ((const float4*)(Cs + r * 128))[c4];
        __half2 h0 = __floats2half2_rn(v.x, v.y);
        __half2 h1 = __floats2half2_rn(v.z, v.w);
        uint2 u;
        u.x = *reinterpret_cast<unsigned*>(&h0);
        u.y = *reinterpret_cast<unsigned*>(&h1);
        ((uint2*)(g_xw + (size_t)rg * D_H))[c4] = u;
    }
}

// ---------------------------------------------------------------------------
// gather-aggregate (R8 form): one warp per dst node, uint2 = 4 halves/lane.
// Pre-scaled tables: acc = table[node] + sum_s table[s]; result = acc*dinv[node]
// LAYER==1: h = relu(result + b); store fp16(h * dinv) -> g_h ; reset cursor
// LAYER==2: store fp16(result) -> g_aggh
// ---------------------------------------------------------------------------
__device__ __forceinline__ void h4_add(float4& acc, uint2 u) {
    __half2 a = *reinterpret_cast<__half2*>(&u.x);
    __half2 b = *reinterpret_cast<__half2*>(&u.y);
    float2 fa = __half22float2(a);
    float2 fb = __half22float2(b);
    acc.x += fa.x; acc.y += fa.y; acc.z += fb.x; acc.w += fb.y;
}

template <int LAYER>
__global__ void k_agg(const float* __restrict__ bias) {
    const __half* table = (LAYER == 1) ? g_xw : g_h;

    int gtid = blockIdx.x * blockDim.x + threadIdx.x;
    int node = gtid >> 5;
    int lane = gtid & 31;
    if (node >= N_NODES) return;

    const int start = g_row_start[node];
    const int end   = g_row_start[node + 1];
    const float dd  = g_dinv[node];

    float4 acc = make_float4(0.f, 0.f, 0.f, 0.f);
    h4_add(acc, __ldg((const uint2*)(table + (size_t)node * D_H) + lane));  // self

    int i = start;
    for (; i + 4 <= end; i += 4) {
        int s0 = g_csr_src[i + 0];
        int s1 = g_csr_src[i + 1];
        int s2 = g_csr_src[i + 2];
        int s3 = g_csr_src[i + 3];
        uint2 u0 = __ldg((const uint2*)(table + (size_t)s0 * D_H) + lane);
        uint2 u1 = __ldg((const uint2*)(table + (size_t)s1 * D_H) + lane);
        uint2 u2 = __ldg((const uint2*)(table + (size_t)s2 * D_H) + lane);
        uint2 u3 = __ldg((const uint2*)(table + (size_t)s3 * D_H) + lane);
        h4_add(acc, u0);
        h4_add(acc, u1);
        h4_add(acc, u2);
        h4_add(acc, u3);
    }
    for (; i < end; ++i) {
        int s = g_csr_src[i];
        h4_add(acc, __ldg((const uint2*)(table + (size_t)s * D_H) + lane));
    }

    acc.x *= dd; acc.y *= dd; acc.z *= dd; acc.w *= dd;

    uint2 o;
    if (LAYER == 1) {
        float4 b = ((const float4*)bias)[lane];
        float hx = fmaxf(acc.x + b.x, 0.0f) * dd;
        float hy = fmaxf(acc.y + b.y, 0.0f) * dd;
        float hz = fmaxf(acc.z + b.z, 0.0f) * dd;
        float hw = fmaxf(acc.w + b.w, 0.0f) * dd;
        __half2 h0 = __floats2half2_rn(hx, hy);
        __half2 h1 = __floats2half2_rn(hz, hw);
        o.x = *reinterpret_cast<unsigned*>(&h0);
        o.y = *reinterpret_cast<unsigned*>(&h1);
        ((uint2*)(g_h + (size_t)node * D_H))[lane] = o;
        if (lane == 0) g_cursor[node] = 0;       // reset for next replay
    } else {
        __half2 h0 = __floats2half2_rn(acc.x, acc.y);
        __half2 h1 = __floats2half2_rn(acc.z, acc.w);
        o.x = *reinterpret_cast<unsigned*>(&h0);
        o.y = *reinterpret_cast<unsigned*>(&h1);
        ((uint2*)(g_aggh + (size_t)node * D_H))[lane] = o;
    }
}

// ---------------------------------------------------------------------------
// GEMM2 (tensor cores) + VGAE epilogue:
//   [mu | ls] = g_aggh @ [Wmu|Wls] ; z = mu+bmu + eps*exp(ls+bls)
// A from global fp16 (padded rows 0); B from GLOBAL fp16 g_w2h (L2-hit);
// smem = 32 KB (C only) -> 7 CTAs/SM.
// ---------------------------------------------------------------------------
__global__ void k_gemm2(const float* __restrict__ bmu,
                        const float* __restrict__ bls,
                        const float* __restrict__ eps,
                        float* __restrict__ out) {
    __shared__ __align__(16) float Cs[64 * 128];   // 32 KB

    const int tid  = threadIdx.x;
    const int row0 = blockIdx.x * 64;

    const int wid = tid >> 5, wr = wid & 3, wc = wid >> 2;
    const __half* Ag = g_aggh + (size_t)(row0 + wr * 16) * D_H;

    wmma::fragment<wmma::accumulator, 16, 16, 16, float> fc[4];
    #pragma unroll
    for (int c = 0; c < 4; ++c) wmma::fill_fragment(fc[c], 0.0f);

    #pragma unroll
    for (int k = 0; k < 8; ++k) {
        wmma::fragment<wmma::matrix_a, 16, 16, 16, __half, wmma::row_major> fa;
        wmma::load_matrix_sync(fa, Ag + k * 16, 128);
        #pragma unroll
        for (int c = 0; c < 4; ++c) {
            wmma::fragment<wmma::matrix_b, 16, 16, 16, __half, wmma::row_major> fb;
            wmma::load_matrix_sync(fb, g_w2h + (k * 16) * 128 + wc * 64 + c * 16, 128);
            wmma::mma_sync(fc[c], fa, fb, fc[c]);
        }
    }

    #pragma unroll
    for (int c = 0; c < 4; ++c)
        wmma::store_matrix_sync(Cs + (wr * 16) * 128 + wc * 64 + c * 16, fc[c],
                                128, wmma::mem_row_major);
    __syncthreads();

    const size_t seg = (size_t)N_NODES * D_Z;
    for (int i = tid; i < 64 * 64; i += 256) {
        int r = i >> 6, c = i & 63;
        int rg = row0 + r;
        if (rg >= N_NODES) continue;
        float mu = Cs[r * 128 + c]      + bmu[c];
        float ls = Cs[r * 128 + 64 + c] + bls[c];
        size_t off = (size_t)rg * D_Z + c;
        out[off]           = mu + eps[off] * expf(ls);
        out[seg + off]     = mu;
        out[2 * seg + off] = ls;
    }
}

// ---------------------------------------------------------------------------
extern "C" void kernel_launch(void* const* d_in, const int* in_sizes, int n_in,
                              void* d_out, int out_size) {
    const float* x   = (const float*)d_in[0];
    const int*   ei  = (const int*)d_in[1];     // [2, E] int32
    const float* eps = (const float*)d_in[2];
    const float* W1  = (const float*)d_in[3];
    const float* b1  = (const float*)d_in[4];
    const float* Wmu = (const float*)d_in[5];
    const float* bmu = (const float*)d_in[6];
    const float* Wls = (const float*)d_in[7];
    const float* bls = (const float*)d_in[8];
    float*       out = (float*)d_out;

    const int* src = ei;
    const int* dst = ei + E_EDGES;

    // CSR build (counters arrive zeroed: load-time init + in-kernel resets)
    k_count      <<<(E_EDGES + 255) / 256, 256>>>(dst);
    k_chunk_sum  <<<NCHUNKS, CHUNK>>>();
    k_scan_chunks<<<1, 128>>>();
    k_chunk_scan <<<NCHUNKS, CHUNK>>>();
    k_scatter    <<<(E_EDGES + 255) / 256, 256>>>(src, dst);

    // weight fp16 conversion
    k_cvt_w<<<(2 * D_IN * D_H + 255) / 256, 256>>>(W1, Wmu, Wls);

    // layer 1: tensor-core transform (pre-scaled fp16 table)
    k_gemm1<<<N_PAD / 64, 256>>>(x);

    // aggregations (warp per node)
    {
        long long total = (long long)N_NODES * 32;
        int blocks = (int)((total + 255) / 256);
        k_agg<1><<<blocks, 256>>>(b1);
        k_agg<2><<<blocks, 256>>>(nullptr);
    }

    // output tensor-core GEMM + reparameterization
    k_gemm2<<<N_PAD / 64, 256>>>(bmu, bls, eps, out);
}

// round 11
// speedup vs baseline: 1.7036x; 1.0371x over previous
#include <cuda_runtime.h>
#include <cuda_fp16.h>
#include <mma.h>
#include <math.h>

using namespace nvcuda;

#define N_NODES 50000
#define N_PAD   50048              // 782 * 64
#define D_IN    128
#define D_H     128
#define D_Z     64
#define E_EDGES 800000

#define CHUNK   512
#define NCHUNKS ((N_NODES + CHUNK - 1) / CHUNK)   // 98

// ---- scratch (device globals; zero-init at load, re-zeroed in-kernel) ----
__device__ int   g_cnt      [N_NODES];       // reset by k_chunk_scan
__device__ int   g_cursor   [N_NODES];       // reset by k_agg<1>
__device__ int   g_row_start[N_NODES + 1];
__device__ int   g_chunk_sum[NCHUNKS];
__device__ int   g_csr_src  [E_EDGES];
__device__ float g_dinv     [N_NODES];
__device__ __align__(16) __half g_w1h [D_IN * D_H];     // fp16 W1
__device__ __align__(16) __half g_w2h [D_H * 128];      // fp16 [Wmu | Wls]
__device__ __align__(16) __half g_xw  [N_NODES * D_H];  // (X@W1) * dinv[row]
__device__ __align__(16) __half g_h   [N_NODES * D_H];  // hidden * dinv[row]
__device__ __align__(16) __half g_aggh[(size_t)N_PAD * D_H]; // A_norm@hidden (padded rows stay 0)

// ---------------------------------------------------------------------------
// fused: degree count + weight fp16 conversion (independent work)
// ---------------------------------------------------------------------------
__global__ void k_count_cvt(const int* __restrict__ dst,
                            const float* __restrict__ W1,
                            const float* __restrict__ Wmu,
                            const float* __restrict__ Wls) {
    int e = blockIdx.x * blockDim.x + threadIdx.x;
    if (e < E_EDGES) {
        int d = dst[e];
        if ((unsigned)d < N_NODES) atomicAdd(&g_cnt[d], 1);
    }
    if (e < 2 * D_IN * D_H) {
        if (e < D_IN * D_H) {
            g_w1h[e] = __float2half(W1[e]);
        } else {
            int j = e - D_IN * D_H;
            int k = j >> 7, n = j & 127;
            float v = (n < 64) ? Wmu[k * 64 + n] : Wls[k * 64 + (n - 64)];
            g_w2h[j] = __float2half(v);
        }
    }
}

// ---------------------------------------------------------------------------
// per-512-chunk totals
// ---------------------------------------------------------------------------
__global__ void k_chunk_sum() {
    __shared__ int sh[CHUNK];
    int t = threadIdx.x;
    int i = blockIdx.x * CHUNK + t;
    int v = (i < N_NODES) ? g_cnt[i] : 0;
    sh[t] = v;
    __syncthreads();
    for (int off = CHUNK / 2; off > 0; off >>= 1) {
        if (t < off) sh[t] += sh[t + off];
        __syncthreads();
    }
    if (t == 0) g_chunk_sum[blockIdx.x] = sh[0];
}

// ---------------------------------------------------------------------------
// fused: per-block chunk-offset reduction + in-chunk exclusive scan
// + dinv = rsqrt(cnt+1) + cnt reset
// ---------------------------------------------------------------------------
__global__ void k_chunk_scan() {
    __shared__ int sh[CHUNK];
    __shared__ int s_off;
    const int t = threadIdx.x;
    const int b = blockIdx.x;

    // offset = sum of chunk sums below this block (<=97 values)
    {
        int p = (t < NCHUNKS && t < b) ? g_chunk_sum[t] : 0;
        sh[t] = p;
        __syncthreads();
        for (int off = CHUNK / 2; off > 0; off >>= 1) {
            if (t < off) sh[t] += sh[t + off];
            __syncthreads();
        }
        if (t == 0) s_off = sh[0];
        __syncthreads();
    }
    const int chunk_off = s_off;
    __syncthreads();

    int i = b * CHUNK + t;
    int v = (i < N_NODES) ? g_cnt[i] : 0;
    sh[t] = v;
    __syncthreads();
    for (int off = 1; off < CHUNK; off <<= 1) {
        int add = (t >= off) ? sh[t - off] : 0;
        __syncthreads();
        sh[t] += add;
        __syncthreads();
    }
    if (i < N_NODES) {
        g_row_start[i] = sh[t] - v + chunk_off;
        g_dinv[i] = rsqrtf((float)(v + 1));     // +1 self-loop
        g_cnt[i] = 0;                           // reset for next replay
    }
    // last chunk also writes the grand total
    if (b == NCHUNKS - 1 && t == CHUNK - 1)
        g_row_start[N_NODES] = chunk_off + sh[CHUNK - 1];
}

// ---------------------------------------------------------------------------
// fused: CSR scatter (blocks 0..SCAT_BLOCKS-1)  ||  GEMM1 (remaining blocks)
// Both depend only on the scan output; mutually independent.
// GEMM1: g_xw = fp16( (x*dinv[row]) @ W1 ), B from global fp16 (L2-hit).
// ---------------------------------------------------------------------------
#define SCAT_BLOCKS ((E_EDGES + 255) / 256)     // 3125
#define GEMM1_BLOCKS (N_PAD / 64)               // 782

__global__ __launch_bounds__(256) void k_scatter_gemm1(
        const int* __restrict__ src,
        const int* __restrict__ dst,
        const float* __restrict__ x) {
    __shared__ __align__(16) char smraw[32768];

    if (blockIdx.x < SCAT_BLOCKS) {
        int e = blockIdx.x * 256 + threadIdx.x;
        if (e >= E_EDGES) return;
        int d = dst[e];
        int s = src[e];
        if ((unsigned)d >= N_NODES || (unsigned)s >= N_NODES) return;
        int pos = g_row_start[d] + atomicAdd(&g_cursor[d], 1);
        g_csr_src[pos] = s;
        return;
    }

    // ----- GEMM1 role -----
    __half* Ah = (__half*)smraw;              // 64x128 fp16 = 16 KB
    float*  Cs = (float*)smraw;               // 64x128 f32 = 32 KB (overlays A)

    const int tid  = threadIdx.x;
    const int row0 = (blockIdx.x - SCAT_BLOCKS) * 64;

    for (int i = tid; i < 64 * 32; i += 256) {
        int r = i >> 5, c4 = i & 31;
        int rg = row0 + r;
        float4 v = make_float4(0.f, 0.f, 0.f, 0.f);
        float di = 0.0f;
        if (rg < N_NODES) {
            v  = ((const float4*)(x + (size_t)rg * D_IN))[c4];
            di = g_dinv[rg];
        }
        __half2 h0 = __floats2half2_rn(v.x * di, v.y * di);
        __half2 h1 = __floats2half2_rn(v.z * di, v.w * di);
        uint2 u;
        u.x = *reinterpret_cast<unsigned*>(&h0);
        u.y = *reinterpret_cast<unsigned*>(&h1);
        ((uint2*)Ah)[i] = u;
    }
    __syncthreads();

    const int wid = tid >> 5, wr = wid & 3, wc = wid >> 2;

    wmma::fragment<wmma::accumulator, 16, 16, 16, float> fc[4];
    #pragma unroll
    for (int c = 0; c < 4; ++c) wmma::fill_fragment(fc[c], 0.0f);

    #pragma unroll
    for (int k = 0; k < 8; ++k) {
        wmma::fragment<wmma::matrix_a, 16, 16, 16, __half, wmma::row_major> fa;
        wmma::load_matrix_sync(fa, Ah + (wr * 16) * 128 + k * 16, 128);
        #pragma unroll
        for (int c = 0; c < 4; ++c) {
            wmma::fragment<wmma::matrix_b, 16, 16, 16, __half, wmma::row_major> fb;
            wmma::load_matrix_sync(fb, g_w1h + (k * 16) * 128 + wc * 64 + c * 16, 128);
            wmma::mma_sync(fc[c], fa, fb, fc[c]);
        }
    }
    __syncthreads();

    #pragma unroll
    for (int c = 0; c < 4; ++c)
        wmma::store_matrix_sync(Cs + (wr * 16) * 128 + wc * 64 + c * 16, fc[c],
                                128, wmma::mem_row_major);
    __syncthreads();

    for (int i = tid; i < 64 * 32; i += 256) {
        int r = i >> 5, c4 = i & 31;
        int rg = row0 + r;
        if (rg >= N_NODES) continue;
        float4 v = ((const float4*)(Cs + r * 128))[c4];
        __half2 h0 = __floats2half2_rn(v.x, v.y);
        __half2 h1 = __floats2half2_rn(v.z, v.w);
        uint2 u;
        u.x = *reinterpret_cast<unsigned*>(&h0);
        u.y = *reinterpret_cast<unsigned*>(&h1);
        ((uint2*)(g_xw + (size_t)rg * D_H))[c4] = u;
    }
}

// ---------------------------------------------------------------------------
// gather-aggregate: one warp per dst node, uint2 = 4 halves/lane, unroll 8.
// Pre-scaled tables: acc = table[node] + sum_s table[s]; result = acc*dinv[node]
// LAYER==1: h = relu(result + b); store fp16(h * dinv) -> g_h ; reset cursor
// LAYER==2: store fp16(result) -> g_aggh
// ---------------------------------------------------------------------------
__device__ __forceinline__ void h4_add(float4& acc, uint2 u) {
    __half2 a = *reinterpret_cast<__half2*>(&u.x);
    __half2 b = *reinterpret_cast<__half2*>(&u.y);
    float2 fa = __half22float2(a);
    float2 fb = __half22float2(b);
    acc.x += fa.x; acc.y += fa.y; acc.z += fb.x; acc.w += fb.y;
}

template <int LAYER>
__global__ void k_agg(const float* __restrict__ bias) {
    const __half* table = (LAYER == 1) ? g_xw : g_h;

    int gtid = blockIdx.x * blockDim.x + threadIdx.x;
    int node = gtid >> 5;
    int lane = gtid & 31;
    if (node >= N_NODES) return;

    const int start = g_row_start[node];
    const int end   = g_row_start[node + 1];
    const float dd  = g_dinv[node];

    float4 acc = make_float4(0.f, 0.f, 0.f, 0.f);
    h4_add(acc, __ldg((const uint2*)(table + (size_t)node * D_H) + lane));  // self

    int i = start;
    for (; i + 8 <= end; i += 8) {
        int s0 = g_csr_src[i + 0];
        int s1 = g_csr_src[i + 1];
        int s2 = g_csr_src[i + 2];
        int s3 = g_csr_src[i + 3];
        int s4 = g_csr_src[i + 4];
        int s5 = g_csr_src[i + 5];
        int s6 = g_csr_src[i + 6];
        int s7 = g_csr_src[i + 7];
        uint2 u0 = __ldg((const uint2*)(table + (size_t)s0 * D_H) + lane);
        uint2 u1 = __ldg((const uint2*)(table + (size_t)s1 * D_H) + lane);
        uint2 u2 = __ldg((const uint2*)(table + (size_t)s2 * D_H) + lane);
        uint2 u3 = __ldg((const uint2*)(table + (size_t)s3 * D_H) + lane);
        uint2 u4 = __ldg((const uint2*)(table + (size_t)s4 * D_H) + lane);
        uint2 u5 = __ldg((const uint2*)(table + (size_t)s5 * D_H) + lane);
        uint2 u6 = __ldg((const uint2*)(table + (size_t)s6 * D_H) + lane);
        uint2 u7 = __ldg((const uint2*)(table + (size_t)s7 * D_H) + lane);
        h4_add(acc, u0); h4_add(acc, u1); h4_add(acc, u2); h4_add(acc, u3);
        h4_add(acc, u4); h4_add(acc, u5); h4_add(acc, u6); h4_add(acc, u7);
    }
    for (; i < end; ++i) {
        int s = g_csr_src[i];
        h4_add(acc, __ldg((const uint2*)(table + (size_t)s * D_H) + lane));
    }

    acc.x *= dd; acc.y *= dd; acc.z *= dd; acc.w *= dd;

    uint2 o;
    if (LAYER == 1) {
        float4 b = ((const float4*)bias)[lane];
        float hx = fmaxf(acc.x + b.x, 0.0f) * dd;
        float hy = fmaxf(acc.y + b.y, 0.0f) * dd;
        float hz = fmaxf(acc.z + b.z, 0.0f) * dd;
        float hw = fmaxf(acc.w + b.w, 0.0f) * dd;
        __half2 h0 = __floats2half2_rn(hx, hy);
        __half2 h1 = __floats2half2_rn(hz, hw);
        o.x = *reinterpret_cast<unsigned*>(&h0);
        o.y = *reinterpret_cast<unsigned*>(&h1);
        ((uint2*)(g_h + (size_t)node * D_H))[lane] = o;
        if (lane == 0) g_cursor[node] = 0;       // reset for next replay
    } else {
        __half2 h0 = __floats2half2_rn(acc.x, acc.y);
        __half2 h1 = __floats2half2_rn(acc.z, acc.w);
        o.x = *reinterpret_cast<unsigned*>(&h0);
        o.y = *reinterpret_cast<unsigned*>(&h1);
        ((uint2*)(g_aggh + (size_t)node * D_H))[lane] = o;
    }
}

// ---------------------------------------------------------------------------
// GEMM2 (tensor cores) + VGAE epilogue:
//   [mu | ls] = g_aggh @ [Wmu|Wls] ; z = mu+bmu + eps*exp(ls+bls)
// ---------------------------------------------------------------------------
__global__ void k_gemm2(const float* __restrict__ bmu,
                        const float* __restrict__ bls,
                        const float* __restrict__ eps,
                        float* __restrict__ out) {
    __shared__ __align__(16) float Cs[64 * 128];   // 32 KB

    const int tid  = threadIdx.x;
    const int row0 = blockIdx.x * 64;

    const int wid = tid >> 5, wr = wid & 3, wc = wid >> 2;
    const __half* Ag = g_aggh + (size_t)(row0 + wr * 16) * D_H;

    wmma::fragment<wmma::accumulator, 16, 16, 16, float> fc[4];
    #pragma unroll
    for (int c = 0; c < 4; ++c) wmma::fill_fragment(fc[c], 0.0f);

    #pragma unroll
    for (int k = 0; k < 8; ++k) {
        wmma::fragment<wmma::matrix_a, 16, 16, 16, __half, wmma::row_major> fa;
        wmma::load_matrix_sync(fa, Ag + k * 16, 128);
        #pragma unroll
        for (int c = 0; c < 4; ++c) {
            wmma::fragment<wmma::matrix_b, 16, 16, 16, __half, wmma::row_major> fb;
            wmma::load_matrix_sync(fb, g_w2h + (k * 16) * 128 + wc * 64 + c * 16, 128);
            wmma::mma_sync(fc[c], fa, fb, fc[c]);
        }
    }

    #pragma unroll
    for (int c = 0; c < 4; ++c)
        wmma::store_matrix_sync(Cs + (wr * 16) * 128 + wc * 64 + c * 16, fc[c],
                                128, wmma::mem_row_major);
    __syncthreads();

    const size_t seg = (size_t)N_NODES * D_Z;
    for (int i = tid; i < 64 * 64; i += 256) {
        int r = i >> 6, c = i & 63;
        int rg = row0 + r;
        if (rg >= N_NODES) continue;
        float mu = Cs[r * 128 + c]      + bmu[c];
        float ls = Cs[r * 128 + 64 + c] + bls[c];
        size_t off = (size_t)rg * D_Z + c;
        out[off]           = mu + eps[off] * expf(ls);
        out[seg + off]     = mu;
        out[2 * seg + off] = ls;
    }
}

// ---------------------------------------------------------------------------
extern "C" void kernel_launch(void* const* d_in, const int* in_sizes, int n_in,
                              void* d_out, int out_size) {
    const float* x   = (const float*)d_in[0];
    const int*   ei  = (const int*)d_in[1];     // [2, E] int32
    const float* eps = (const float*)d_in[2];
    const float* W1  = (const float*)d_in[3];
    const float* b1  = (const float*)d_in[4];
    const float* Wmu = (const float*)d_in[5];
    const float* bmu = (const float*)d_in[6];
    const float* Wls = (const float*)d_in[7];
    const float* bls = (const float*)d_in[8];
    float*       out = (float*)d_out;

    const int* src = ei;
    const int* dst = ei + E_EDGES;

    // 1. degree count + weight conversion (fused)
    k_count_cvt<<<SCAT_BLOCKS, 256>>>(dst, W1, Wmu, Wls);
    // 2. chunk totals
    k_chunk_sum<<<NCHUNKS, CHUNK>>>();
    // 3. offsets + in-chunk scan + dinv (fused)
    k_chunk_scan<<<NCHUNKS, CHUNK>>>();
    // 4. CSR scatter || GEMM1 (fused, independent roles)
    k_scatter_gemm1<<<SCAT_BLOCKS + GEMM1_BLOCKS, 256>>>(src, dst, x);
    // 5-6. aggregations (warp per node)
    {
        long long total = (long long)N_NODES * 32;
        int blocks = (int)((total + 255) / 256);
        k_agg<1><<<blocks, 256>>>(b1);
        k_agg<2><<<blocks, 256>>>(nullptr);
    }
    // 7. output tensor-core GEMM + reparameterization
    k_gemm2<<<N_PAD / 64, 256>>>(bmu, bls, eps, out);
}

// round 12
// speedup vs baseline: 1.8143x; 1.0650x over previous
#include <cuda_runtime.h>
#include <cuda_fp16.h>
#include <mma.h>
#include <math.h>

using namespace nvcuda;

#define N_NODES 50000
#define N_PAD   50048              // 782 * 64
#define D_IN    128
#define D_H     128
#define D_Z     64
#define E_EDGES 800000

#define CHUNK   512
#define NCHUNKS ((N_NODES + CHUNK - 1) / CHUNK)   // 98

// ---- scratch (device globals; zero-init at load, re-zeroed in-kernel) ----
__device__ int   g_cnt      [N_NODES];       // reset by k_chunk_scan
__device__ int   g_cursor   [N_NODES];       // (re)written by k_chunk_scan
__device__ int   g_row_start[N_NODES + 1];
__device__ int   g_chunk_sum[NCHUNKS];
__device__ int   g_csr_src  [E_EDGES];
__device__ float g_dinv     [N_NODES];
__device__ __align__(16) __half g_w1h [D_IN * D_H];     // fp16 W1
__device__ __align__(16) __half g_w2h [D_H * 128];      // fp16 [Wmu | Wls]
__device__ __align__(16) __half g_xw  [N_NODES * D_H];  // (X@W1) * dinv[row]
__device__ __align__(16) __half g_h   [N_NODES * D_H];  // hidden * dinv[row]
__device__ __align__(16) __half g_aggh[(size_t)N_PAD * D_H]; // A_norm@hidden (padded rows stay 0)

// ---------------------------------------------------------------------------
// fused: degree count + weight fp16 conversion (independent work)
// ---------------------------------------------------------------------------
__global__ void k_count_cvt(const int* __restrict__ dst,
                            const float* __restrict__ W1,
                            const float* __restrict__ Wmu,
                            const float* __restrict__ Wls) {
    int e = blockIdx.x * blockDim.x + threadIdx.x;
    if (e < E_EDGES) {
        int d = dst[e];
        if ((unsigned)d < N_NODES) atomicAdd(&g_cnt[d], 1);
    }
    if (e < 2 * D_IN * D_H) {
        if (e < D_IN * D_H) {
            g_w1h[e] = __float2half(W1[e]);
        } else {
            int j = e - D_IN * D_H;
            int k = j >> 7, n = j & 127;
            float v = (n < 64) ? Wmu[k * 64 + n] : Wls[k * 64 + (n - 64)];
            g_w2h[j] = __float2half(v);
        }
    }
}

// ---------------------------------------------------------------------------
// per-512-chunk totals
// ---------------------------------------------------------------------------
__global__ void k_chunk_sum() {
    __shared__ int sh[CHUNK];
    int t = threadIdx.x;
    int i = blockIdx.x * CHUNK + t;
    int v = (i < N_NODES) ? g_cnt[i] : 0;
    sh[t] = v;
    __syncthreads();
    for (int off = CHUNK / 2; off > 0; off >>= 1) {
        if (t < off) sh[t] += sh[t + off];
        __syncthreads();
    }
    if (t == 0) g_chunk_sum[blockIdx.x] = sh[0];
}

// ---------------------------------------------------------------------------
// fused: per-block chunk-offset reduction + in-chunk exclusive scan
// + dinv + cursor init + cnt reset
// ---------------------------------------------------------------------------
__global__ void k_chunk_scan() {
    __shared__ int sh[CHUNK];
    __shared__ int s_off;
    const int t = threadIdx.x;
    const int b = blockIdx.x;

    {
        int p = (t < NCHUNKS && t < b) ? g_chunk_sum[t] : 0;
        sh[t] = p;
        __syncthreads();
        for (int off = CHUNK / 2; off > 0; off >>= 1) {
            if (t < off) sh[t] += sh[t + off];
            __syncthreads();
        }
        if (t == 0) s_off = sh[0];
        __syncthreads();
    }
    const int chunk_off = s_off;
    __syncthreads();

    int i = b * CHUNK + t;
    int v = (i < N_NODES) ? g_cnt[i] : 0;
    sh[t] = v;
    __syncthreads();
    for (int off = 1; off < CHUNK; off <<= 1) {
        int add = (t >= off) ? sh[t - off] : 0;
        __syncthreads();
        sh[t] += add;
        __syncthreads();
    }
    if (i < N_NODES) {
        int rs = sh[t] - v + chunk_off;
        g_row_start[i] = rs;
        g_cursor[i]    = rs;                    // scatter cursor starts at row base
        g_dinv[i] = rsqrtf((float)(v + 1));     // +1 self-loop
        g_cnt[i] = 0;                           // reset for next replay
    }
    if (b == NCHUNKS - 1 && t == CHUNK - 1)
        g_row_start[N_NODES] = chunk_off + sh[CHUNK - 1];
}

// ---------------------------------------------------------------------------
// fused: CSR scatter (blocks 0..SCAT_BLOCKS-1)  ||  GEMM1 (remaining blocks)
// GEMM1: g_xw = fp16( (x*dinv[row]) @ W1 ), B from global fp16,
//        epilogue fully in-register via HMMA.16816 fragment layout.
// ---------------------------------------------------------------------------
#define SCAT_BLOCKS ((E_EDGES + 255) / 256)     // 3125
#define GEMM1_BLOCKS (N_PAD / 64)               // 782

__global__ __launch_bounds__(256) void k_scatter_gemm1(
        const int* __restrict__ src,
        const int* __restrict__ dst,
        const float* __restrict__ x) {
    __shared__ __align__(16) __half Ah[64 * 128];   // 16 KB

    if (blockIdx.x < SCAT_BLOCKS) {
        int e = blockIdx.x * 256 + threadIdx.x;
        if (e >= E_EDGES) return;
        int d = dst[e];
        int s = src[e];
        if ((unsigned)d >= N_NODES || (unsigned)s >= N_NODES) return;
        int pos = atomicAdd(&g_cursor[d], 1);
        g_csr_src[pos] = s;
        return;
    }

    // ----- GEMM1 role -----
    const int tid  = threadIdx.x;
    const int row0 = (blockIdx.x - SCAT_BLOCKS) * 64;

    for (int i = tid; i < 64 * 32; i += 256) {
        int r = i >> 5, c4 = i & 31;
        int rg = row0 + r;
        float4 v = make_float4(0.f, 0.f, 0.f, 0.f);
        float di = 0.0f;
        if (rg < N_NODES) {
            v  = ((const float4*)(x + (size_t)rg * D_IN))[c4];
            di = g_dinv[rg];
        }
        __half2 h0 = __floats2half2_rn(v.x * di, v.y * di);
        __half2 h1 = __floats2half2_rn(v.z * di, v.w * di);
        uint2 u;
        u.x = *reinterpret_cast<unsigned*>(&h0);
        u.y = *reinterpret_cast<unsigned*>(&h1);
        ((uint2*)Ah)[i] = u;
    }
    __syncthreads();

    const int wid = tid >> 5, wr = wid & 3, wc = wid >> 2;
    const int lane = tid & 31;

    wmma::fragment<wmma::accumulator, 16, 16, 16, float> fc[4];
    #pragma unroll
    for (int c = 0; c < 4; ++c) wmma::fill_fragment(fc[c], 0.0f);

    #pragma unroll
    for (int k = 0; k < 8; ++k) {
        wmma::fragment<wmma::matrix_a, 16, 16, 16, __half, wmma::row_major> fa;
        wmma::load_matrix_sync(fa, Ah + (wr * 16) * 128 + k * 16, 128);
        #pragma unroll
        for (int c = 0; c < 4; ++c) {
            wmma::fragment<wmma::matrix_b, 16, 16, 16, __half, wmma::row_major> fb;
            wmma::load_matrix_sync(fb, g_w1h + (k * 16) * 128 + wc * 64 + c * 16, 128);
            wmma::mma_sync(fc[c], fa, fb, fc[c]);
        }
    }

    // in-register epilogue: fragment (lane,i) -> (row,col), STG __half2
    #pragma unroll
    for (int c = 0; c < 4; ++c) {
        #pragma unroll
        for (int p = 0; p < 4; ++p) {
            int i0  = 2 * p;
            int rg  = row0 + wr * 16 + (lane >> 2) + 8 * (p & 1);
            int col = wc * 64 + c * 16 + (lane & 3) * 2 + 8 * (p >> 1);
            if (rg < N_NODES) {
                __half2 hv = __floats2half2_rn(fc[c].x[i0], fc[c].x[i0 + 1]);
                *(__half2*)(g_xw + (size_t)rg * D_H + col) = hv;
            }
        }
    }
}

// ---------------------------------------------------------------------------
// gather-aggregate: one warp per dst node, uint2 = 4 halves/lane, unroll 8.
// ---------------------------------------------------------------------------
__device__ __forceinline__ void h4_add(float4& acc, uint2 u) {
    __half2 a = *reinterpret_cast<__half2*>(&u.x);
    __half2 b = *reinterpret_cast<__half2*>(&u.y);
    float2 fa = __half22float2(a);
    float2 fb = __half22float2(b);
    acc.x += fa.x; acc.y += fa.y; acc.z += fb.x; acc.w += fb.y;
}

template <int LAYER>
__global__ void k_agg(const float* __restrict__ bias) {
    const __half* table = (LAYER == 1) ? g_xw : g_h;

    int gtid = blockIdx.x * blockDim.x + threadIdx.x;
    int node = gtid >> 5;
    int lane = gtid & 31;
    if (node >= N_NODES) return;

    const int start = g_row_start[node];
    const int end   = g_row_start[node + 1];
    const float dd  = g_dinv[node];

    float4 acc = make_float4(0.f, 0.f, 0.f, 0.f);
    h4_add(acc, __ldg((const uint2*)(table + (size_t)node * D_H) + lane));  // self

    int i = start;
    for (; i + 8 <= end; i += 8) {
        int s0 = g_csr_src[i + 0];
        int s1 = g_csr_src[i + 1];
        int s2 = g_csr_src[i + 2];
        int s3 = g_csr_src[i + 3];
        int s4 = g_csr_src[i + 4];
        int s5 = g_csr_src[i + 5];
        int s6 = g_csr_src[i + 6];
        int s7 = g_csr_src[i + 7];
        uint2 u0 = __ldg((const uint2*)(table + (size_t)s0 * D_H) + lane);
        uint2 u1 = __ldg((const uint2*)(table + (size_t)s1 * D_H) + lane);
        uint2 u2 = __ldg((const uint2*)(table + (size_t)s2 * D_H) + lane);
        uint2 u3 = __ldg((const uint2*)(table + (size_t)s3 * D_H) + lane);
        uint2 u4 = __ldg((const uint2*)(table + (size_t)s4 * D_H) + lane);
        uint2 u5 = __ldg((const uint2*)(table + (size_t)s5 * D_H) + lane);
        uint2 u6 = __ldg((const uint2*)(table + (size_t)s6 * D_H) + lane);
        uint2 u7 = __ldg((const uint2*)(table + (size_t)s7 * D_H) + lane);
        h4_add(acc, u0); h4_add(acc, u1); h4_add(acc, u2); h4_add(acc, u3);
        h4_add(acc, u4); h4_add(acc, u5); h4_add(acc, u6); h4_add(acc, u7);
    }
    for (; i < end; ++i) {
        int s = g_csr_src[i];
        h4_add(acc, __ldg((const uint2*)(table + (size_t)s * D_H) + lane));
    }

    acc.x *= dd; acc.y *= dd; acc.z *= dd; acc.w *= dd;

    uint2 o;
    if (LAYER == 1) {
        float4 b = ((const float4*)bias)[lane];
        float hx = fmaxf(acc.x + b.x, 0.0f) * dd;
        float hy = fmaxf(acc.y + b.y, 0.0f) * dd;
        float hz = fmaxf(acc.z + b.z, 0.0f) * dd;
        float hw = fmaxf(acc.w + b.w, 0.0f) * dd;
        __half2 h0 = __floats2half2_rn(hx, hy);
        __half2 h1 = __floats2half2_rn(hz, hw);
        o.x = *reinterpret_cast<unsigned*>(&h0);
        o.y = *reinterpret_cast<unsigned*>(&h1);
        ((uint2*)(g_h + (size_t)node * D_H))[lane] = o;
    } else {
        __half2 h0 = __floats2half2_rn(acc.x, acc.y);
        __half2 h1 = __floats2half2_rn(acc.z, acc.w);
        o.x = *reinterpret_cast<unsigned*>(&h0);
        o.y = *reinterpret_cast<unsigned*>(&h1);
        ((uint2*)(g_aggh + (size_t)node * D_H))[lane] = o;
    }
}

// ---------------------------------------------------------------------------
// GEMM2 (tensor cores, ZERO smem) + in-register VGAE epilogue.
// warp (wr, wc): rows row0+wr*16; fc[0..1] = mu cols wc*32..+31,
// fc[2..3] = ls cols 64+wc*32..+31 (same output positions).
// z = mu + eps*exp(ls) computed per-thread from matching fragments.
// ---------------------------------------------------------------------------
__global__ __launch_bounds__(256) void k_gemm2(
        const float* __restrict__ bmu,
        const float* __restrict__ bls,
        const float* __restrict__ eps,
        float* __restrict__ out) {
    const int tid  = threadIdx.x;
    const int row0 = blockIdx.x * 64;
    const int wid  = tid >> 5, wr = wid & 3, wc = wid >> 2;
    const int lane = tid & 31;

    const __half* Ag = g_aggh + (size_t)(row0 + wr * 16) * D_H;

    wmma::fragment<wmma::accumulator, 16, 16, 16, float> fc[4];
    #pragma unroll
    for (int c = 0; c < 4; ++c) wmma::fill_fragment(fc[c], 0.0f);

    #pragma unroll
    for (int k = 0; k < 8; ++k) {
        wmma::fragment<wmma::matrix_a, 16, 16, 16, __half, wmma::row_major> fa;
        wmma::load_matrix_sync(fa, Ag + k * 16, 128);
        #pragma unroll
        for (int j = 0; j < 2; ++j) {
            wmma::fragment<wmma::matrix_b, 16, 16, 16, __half, wmma::row_major> fbm;
            wmma::fragment<wmma::matrix_b, 16, 16, 16, __half, wmma::row_major> fbl;
            wmma::load_matrix_sync(fbm, g_w2h + (k * 16) * 128 + wc * 32 + j * 16, 128);
            wmma::load_matrix_sync(fbl, g_w2h + (k * 16) * 128 + 64 + wc * 32 + j * 16, 128);
            wmma::mma_sync(fc[j],     fa, fbm, fc[j]);
            wmma::mma_sync(fc[j + 2], fa, fbl, fc[j + 2]);
        }
    }

    const size_t seg = (size_t)N_NODES * D_Z;
    #pragma unroll
    for (int j = 0; j < 2; ++j) {
        #pragma unroll
        for (int p = 0; p < 4; ++p) {
            int i0  = 2 * p;
            int rg  = row0 + wr * 16 + (lane >> 2) + 8 * (p & 1);
            int col = wc * 32 + j * 16 + (lane & 3) * 2 + 8 * (p >> 1);
            if (rg >= N_NODES) continue;
            float mu0 = fc[j].x[i0]       + bmu[col];
            float mu1 = fc[j].x[i0 + 1]   + bmu[col + 1];
            float ls0 = fc[j + 2].x[i0]     + bls[col];
            float ls1 = fc[j + 2].x[i0 + 1] + bls[col + 1];
            size_t off = (size_t)rg * D_Z + col;
            float2 ev = *(const float2*)(eps + off);
            float2 zv = make_float2(mu0 + ev.x * expf(ls0),
                                    mu1 + ev.y * expf(ls1));
            *(float2*)(out + off)           = zv;
            *(float2*)(out + seg + off)     = make_float2(mu0, mu1);
            *(float2*)(out + 2 * seg + off) = make_float2(ls0, ls1);
        }
    }
}

// ---------------------------------------------------------------------------
extern "C" void kernel_launch(void* const* d_in, const int* in_sizes, int n_in,
                              void* d_out, int out_size) {
    const float* x   = (const float*)d_in[0];
    const int*   ei  = (const int*)d_in[1];     // [2, E] int32
    const float* eps = (const float*)d_in[2];
    const float* W1  = (const float*)d_in[3];
    const float* b1  = (const float*)d_in[4];
    const float* Wmu = (const float*)d_in[5];
    const float* bmu = (const float*)d_in[6];
    const float* Wls = (const float*)d_in[7];
    const float* bls = (const float*)d_in[8];
    float*       out = (float*)d_out;

    const int* src = ei;
    const int* dst = ei + E_EDGES;

    k_count_cvt<<<SCAT_BLOCKS, 256>>>(dst, W1, Wmu, Wls);
    k_chunk_sum<<<NCHUNKS, CHUNK>>>();
    k_chunk_scan<<<NCHUNKS, CHUNK>>>();
    k_scatter_gemm1<<<SCAT_BLOCKS + GEMM1_BLOCKS, 256>>>(src, dst, x);
    {
        long long total = (long long)N_NODES * 32;
        int blocks = (int)((total + 255) / 256);
        k_agg<1><<<blocks, 256>>>(b1);
        k_agg<2><<<blocks, 256>>>(nullptr);
    }
    k_gemm2<<<N_PAD / 64, 256>>>(bmu, bls, eps, out);
}

// round 13
// speedup vs baseline: 2.4795x; 1.3666x over previous
#include <cuda_runtime.h>
#include <cuda_fp16.h>
#include <mma.h>
#include <math.h>

using namespace nvcuda;

#define N_NODES 50000
#define N_PAD   50048              // multiple of 32
#define D_IN    128
#define D_H     128
#define D_Z     64
#define E_EDGES 800000

#define CHUNK   512
#define NCHUNKS ((N_NODES + CHUNK - 1) / CHUNK)   // 98

#define LDP 136                     // padded smem stride (halves): conflict-free LDSM

// ---- scratch (device globals; zero-init at load, re-zeroed in-kernel) ----
__device__ int   g_cnt      [N_NODES];       // reset by k_chunk_scan
__device__ int   g_cursor   [N_NODES];       // (re)written by k_chunk_scan
__device__ int   g_row_start[N_NODES + 1];
__device__ int   g_chunk_sum[NCHUNKS];
__device__ int   g_csr_src  [E_EDGES];
__device__ float g_dinv     [N_NODES];
__device__ __align__(16) __half g_w1h [D_IN * D_H];     // fp16 W1
__device__ __align__(16) __half g_w2h [D_H * 128];      // fp16 [Wmu | Wls]
__device__ __align__(16) __half g_xw  [N_NODES * D_H];  // (X@W1) * dinv[row]
__device__ __align__(16) __half g_h   [N_NODES * D_H];  // hidden * dinv[row]
__device__ __align__(16) __half g_aggh[(size_t)N_PAD * D_H]; // A_norm@hidden (padded rows stay 0)

// ---------------------------------------------------------------------------
// fused: degree count + weight fp16 conversion
// ---------------------------------------------------------------------------
__global__ void k_count_cvt(const int* __restrict__ dst,
                            const float* __restrict__ W1,
                            const float* __restrict__ Wmu,
                            const float* __restrict__ Wls) {
    int e = blockIdx.x * blockDim.x + threadIdx.x;
    if (e < E_EDGES) {
        int d = dst[e];
        if ((unsigned)d < N_NODES) atomicAdd(&g_cnt[d], 1);
    }
    if (e < 2 * D_IN * D_H) {
        if (e < D_IN * D_H) {
            g_w1h[e] = __float2half(W1[e]);
        } else {
            int j = e - D_IN * D_H;
            int k = j >> 7, n = j & 127;
            float v = (n < 64) ? Wmu[k * 64 + n] : Wls[k * 64 + (n - 64)];
            g_w2h[j] = __float2half(v);
        }
    }
}

// ---------------------------------------------------------------------------
// per-512-chunk totals
// ---------------------------------------------------------------------------
__global__ void k_chunk_sum() {
    __shared__ int sh[CHUNK];
    int t = threadIdx.x;
    int i = blockIdx.x * CHUNK + t;
    int v = (i < N_NODES) ? g_cnt[i] : 0;
    sh[t] = v;
    __syncthreads();
    for (int off = CHUNK / 2; off > 0; off >>= 1) {
        if (t < off) sh[t] += sh[t + off];
        __syncthreads();
    }
    if (t == 0) g_chunk_sum[blockIdx.x] = sh[0];
}

// ---------------------------------------------------------------------------
// fused: offsets + in-chunk scan + dinv + cursor init + cnt reset
// ---------------------------------------------------------------------------
__global__ void k_chunk_scan() {
    __shared__ int sh[CHUNK];
    __shared__ int s_off;
    const int t = threadIdx.x;
    const int b = blockIdx.x;

    {
        int p = (t < NCHUNKS && t < b) ? g_chunk_sum[t] : 0;
        sh[t] = p;
        __syncthreads();
        for (int off = CHUNK / 2; off > 0; off >>= 1) {
            if (t < off) sh[t] += sh[t + off];
            __syncthreads();
        }
        if (t == 0) s_off = sh[0];
        __syncthreads();
    }
    const int chunk_off = s_off;
    __syncthreads();

    int i = b * CHUNK + t;
    int v = (i < N_NODES) ? g_cnt[i] : 0;
    sh[t] = v;
    __syncthreads();
    for (int off = 1; off < CHUNK; off <<= 1) {
        int add = (t >= off) ? sh[t - off] : 0;
        __syncthreads();
        sh[t] += add;
        __syncthreads();
    }
    if (i < N_NODES) {
        int rs = sh[t] - v + chunk_off;
        g_row_start[i] = rs;
        g_cursor[i]    = rs;
        g_dinv[i] = rsqrtf((float)(v + 1));
        g_cnt[i] = 0;
    }
    if (b == NCHUNKS - 1 && t == CHUNK - 1)
        g_row_start[N_NODES] = chunk_off + sh[CHUNK - 1];
}

// ---------------------------------------------------------------------------
// fused: GEMM1 (blocks 0..GEMM1_BLOCKS-1, long, start first)
//        || CSR scatter (remaining blocks, short, fill behind)
// GEMM1: g_xw = fp16( (x*dinv) @ W1 ); 32 rows/block; padded smem (LDP=136);
//        in-register fragment epilogue.
// ---------------------------------------------------------------------------
#define GEMM1_BLOCKS (N_PAD / 32)               // 1564
#define SCAT_BLOCKS  ((E_EDGES + 255) / 256)    // 3125

__global__ __launch_bounds__(256) void k_gemm1_scatter(
        const int* __restrict__ src,
        const int* __restrict__ dst,
        const float* __restrict__ x) {
    __shared__ __align__(16) __half Ah[32  * LDP];   //  8.7 KB
    __shared__ __align__(16) __half Bh[128 * LDP];   // 34.8 KB

    if (blockIdx.x >= GEMM1_BLOCKS) {
        int e = (blockIdx.x - GEMM1_BLOCKS) * 256 + threadIdx.x;
        if (e >= E_EDGES) return;
        int d = dst[e];
        int s = src[e];
        if ((unsigned)d >= N_NODES || (unsigned)s >= N_NODES) return;
        int pos = atomicAdd(&g_cursor[d], 1);
        g_csr_src[pos] = s;
        return;
    }

    const int tid  = threadIdx.x;
    const int row0 = blockIdx.x * 32;

    // stage A (pre-scaled by dinv) into padded smem
    for (int i = tid; i < 32 * 32; i += 256) {
        int r = i >> 5, c4 = i & 31;
        int rg = row0 + r;
        float4 v = make_float4(0.f, 0.f, 0.f, 0.f);
        float di = 0.0f;
        if (rg < N_NODES) {
            v  = ((const float4*)(x + (size_t)rg * D_IN))[c4];
            di = g_dinv[rg];
        }
        __half2 h0 = __floats2half2_rn(v.x * di, v.y * di);
        __half2 h1 = __floats2half2_rn(v.z * di, v.w * di);
        uint2 u;
        u.x = *reinterpret_cast<unsigned*>(&h0);
        u.y = *reinterpret_cast<unsigned*>(&h1);
        ((uint2*)(Ah + r * LDP))[c4] = u;
    }
    // stage B into padded smem
    for (int i = tid; i < 128 * 32; i += 256) {
        int r = i >> 5, c4 = i & 31;
        ((uint2*)(Bh + r * LDP))[c4] = ((const uint2*)(g_w1h + r * D_H))[c4];
    }
    __syncthreads();

    // 8 warps = 2 row-tiles x 4 col-tiles (32 cols each)
    const int wid = tid >> 5, wr = wid & 1, wc = wid >> 1;
    const int lane = tid & 31;

    wmma::fragment<wmma::accumulator, 16, 16, 16, float> fc[2];
    wmma::fill_fragment(fc[0], 0.0f);
    wmma::fill_fragment(fc[1], 0.0f);

    #pragma unroll
    for (int k = 0; k < 8; ++k) {
        wmma::fragment<wmma::matrix_a, 16, 16, 16, __half, wmma::row_major> fa;
        wmma::load_matrix_sync(fa, Ah + (wr * 16) * LDP + k * 16, LDP);
        #pragma unroll
        for (int c = 0; c < 2; ++c) {
            wmma::fragment<wmma::matrix_b, 16, 16, 16, __half, wmma::row_major> fb;
            wmma::load_matrix_sync(fb, Bh + (k * 16) * LDP + wc * 32 + c * 16, LDP);
            wmma::mma_sync(fc[c], fa, fb, fc[c]);
        }
    }

    // in-register epilogue: fragment (lane,i) -> (row,col), STG __half2
    #pragma unroll
    for (int c = 0; c < 2; ++c) {
        #pragma unroll
        for (int p = 0; p < 4; ++p) {
            int i0  = 2 * p;
            int rg  = row0 + wr * 16 + (lane >> 2) + 8 * (p & 1);
            int col = wc * 32 + c * 16 + (lane & 3) * 2 + 8 * (p >> 1);
            if (rg < N_NODES) {
                __half2 hv = __floats2half2_rn(fc[c].x[i0], fc[c].x[i0 + 1]);
                *(__half2*)(g_xw + (size_t)rg * D_H + col) = hv;
            }
        }
    }
}

// ---------------------------------------------------------------------------
// gather-aggregate: one warp per dst node, uint2 = 4 halves/lane, unroll 8.
// ---------------------------------------------------------------------------
__device__ __forceinline__ void h4_add(float4& acc, uint2 u) {
    __half2 a = *reinterpret_cast<__half2*>(&u.x);
    __half2 b = *reinterpret_cast<__half2*>(&u.y);
    float2 fa = __half22float2(a);
    float2 fb = __half22float2(b);
    acc.x += fa.x; acc.y += fa.y; acc.z += fb.x; acc.w += fb.y;
}

template <int LAYER>
__global__ void k_agg(const float* __restrict__ bias) {
    const __half* table = (LAYER == 1) ? g_xw : g_h;

    int gtid = blockIdx.x * blockDim.x + threadIdx.x;
    int node = gtid >> 5;
    int lane = gtid & 31;
    if (node >= N_NODES) return;

    const int start = g_row_start[node];
    const int end   = g_row_start[node + 1];
    const float dd  = g_dinv[node];

    float4 acc = make_float4(0.f, 0.f, 0.f, 0.f);
    h4_add(acc, __ldg((const uint2*)(table + (size_t)node * D_H) + lane));  // self

    int i = start;
    for (; i + 8 <= end; i += 8) {
        int s0 = g_csr_src[i + 0];
        int s1 = g_csr_src[i + 1];
        int s2 = g_csr_src[i + 2];
        int s3 = g_csr_src[i + 3];
        int s4 = g_csr_src[i + 4];
        int s5 = g_csr_src[i + 5];
        int s6 = g_csr_src[i + 6];
        int s7 = g_csr_src[i + 7];
        uint2 u0 = __ldg((const uint2*)(table + (size_t)s0 * D_H) + lane);
        uint2 u1 = __ldg((const uint2*)(table + (size_t)s1 * D_H) + lane);
        uint2 u2 = __ldg((const uint2*)(table + (size_t)s2 * D_H) + lane);
        uint2 u3 = __ldg((const uint2*)(table + (size_t)s3 * D_H) + lane);
        uint2 u4 = __ldg((const uint2*)(table + (size_t)s4 * D_H) + lane);
        uint2 u5 = __ldg((const uint2*)(table + (size_t)s5 * D_H) + lane);
        uint2 u6 = __ldg((const uint2*)(table + (size_t)s6 * D_H) + lane);
        uint2 u7 = __ldg((const uint2*)(table + (size_t)s7 * D_H) + lane);
        h4_add(acc, u0); h4_add(acc, u1); h4_add(acc, u2); h4_add(acc, u3);
        h4_add(acc, u4); h4_add(acc, u5); h4_add(acc, u6); h4_add(acc, u7);
    }
    for (; i < end; ++i) {
        int s = g_csr_src[i];
        h4_add(acc, __ldg((const uint2*)(table + (size_t)s * D_H) + lane));
    }

    acc.x *= dd; acc.y *= dd; acc.z *= dd; acc.w *= dd;

    uint2 o;
    if (LAYER == 1) {
        float4 b = ((const float4*)bias)[lane];
        float hx = fmaxf(acc.x + b.x, 0.0f) * dd;
        float hy = fmaxf(acc.y + b.y, 0.0f) * dd;
        float hz = fmaxf(acc.z + b.z, 0.0f) * dd;
        float hw = fmaxf(acc.w + b.w, 0.0f) * dd;
        __half2 h0 = __floats2half2_rn(hx, hy);
        __half2 h1 = __floats2half2_rn(hz, hw);
        o.x = *reinterpret_cast<unsigned*>(&h0);
        o.y = *reinterpret_cast<unsigned*>(&h1);
        ((uint2*)(g_h + (size_t)node * D_H))[lane] = o;
    } else {
        __half2 h0 = __floats2half2_rn(acc.x, acc.y);
        __half2 h1 = __floats2half2_rn(acc.z, acc.w);
        o.x = *reinterpret_cast<unsigned*>(&h0);
        o.y = *reinterpret_cast<unsigned*>(&h1);
        ((uint2*)(g_aggh + (size_t)node * D_H))[lane] = o;
    }
}

// ---------------------------------------------------------------------------
// GEMM2 (tensor cores, padded smem) + in-register VGAE epilogue.
// 32 rows/block; warp (wr,wc): rows wr*16, mu cols wc*16, ls cols 64+wc*16.
// ---------------------------------------------------------------------------
__global__ __launch_bounds__(256) void k_gemm2(
        const float* __restrict__ bmu,
        const float* __restrict__ bls,
        const float* __restrict__ eps,
        float* __restrict__ out) {
    __shared__ __align__(16) __half Ah[32  * LDP];   //  8.7 KB
    __shared__ __align__(16) __half Bh[128 * LDP];   // 34.8 KB

    const int tid  = threadIdx.x;
    const int row0 = blockIdx.x * 32;

    // stage A (fp16 copy) and B into padded smem
    for (int i = tid; i < 32 * 32; i += 256) {
        int r = i >> 5, c4 = i & 31;
        ((uint2*)(Ah + r * LDP))[c4] =
            ((const uint2*)(g_aggh + (size_t)(row0 + r) * D_H))[c4];
    }
    for (int i = tid; i < 128 * 32; i += 256) {
        int r = i >> 5, c4 = i & 31;
        ((uint2*)(Bh + r * LDP))[c4] = ((const uint2*)(g_w2h + r * 128))[c4];
    }
    __syncthreads();

    const int wid = tid >> 5, wr = wid & 1, wc = wid >> 1;
    const int lane = tid & 31;

    wmma::fragment<wmma::accumulator, 16, 16, 16, float> fcm, fcl;
    wmma::fill_fragment(fcm, 0.0f);
    wmma::fill_fragment(fcl, 0.0f);

    #pragma unroll
    for (int k = 0; k < 8; ++k) {
        wmma::fragment<wmma::matrix_a, 16, 16, 16, __half, wmma::row_major> fa;
        wmma::load_matrix_sync(fa, Ah + (wr * 16) * LDP + k * 16, LDP);
        wmma::fragment<wmma::matrix_b, 16, 16, 16, __half, wmma::row_major> fbm;
        wmma::fragment<wmma::matrix_b, 16, 16, 16, __half, wmma::row_major> fbl;
        wmma::load_matrix_sync(fbm, Bh + (k * 16) * LDP + wc * 16, LDP);
        wmma::load_matrix_sync(fbl, Bh + (k * 16) * LDP + 64 + wc * 16, LDP);
        wmma::mma_sync(fcm, fa, fbm, fcm);
        wmma::mma_sync(fcl, fa, fbl, fcl);
    }

    const size_t seg = (size_t)N_NODES * D_Z;
    #pragma unroll
    for (int p = 0; p < 4; ++p) {
        int i0  = 2 * p;
        int rg  = row0 + wr * 16 + (lane >> 2) + 8 * (p & 1);
        int col = wc * 16 + (lane & 3) * 2 + 8 * (p >> 1);
        if (rg >= N_NODES) continue;
        float mu0 = fcm.x[i0]     + bmu[col];
        float mu1 = fcm.x[i0 + 1] + bmu[col + 1];
        float ls0 = fcl.x[i0]     + bls[col];
        float ls1 = fcl.x[i0 + 1] + bls[col + 1];
        size_t off = (size_t)rg * D_Z + col;
        float2 ev = *(const float2*)(eps + off);
        float2 zv = make_float2(mu0 + ev.x * expf(ls0),
                                mu1 + ev.y * expf(ls1));
        *(float2*)(out + off)           = zv;
        *(float2*)(out + seg + off)     = make_float2(mu0, mu1);
        *(float2*)(out + 2 * seg + off) = make_float2(ls0, ls1);
    }
}

// ---------------------------------------------------------------------------
extern "C" void kernel_launch(void* const* d_in, const int* in_sizes, int n_in,
                              void* d_out, int out_size) {
    const float* x   = (const float*)d_in[0];
    const int*   ei  = (const int*)d_in[1];     // [2, E] int32
    const float* eps = (const float*)d_in[2];
    const float* W1  = (const float*)d_in[3];
    const float* b1  = (const float*)d_in[4];
    const float* Wmu = (const float*)d_in[5];
    const float* bmu = (const float*)d_in[6];
    const float* Wls = (const float*)d_in[7];
    const float* bls = (const float*)d_in[8];
    float*       out = (float*)d_out;

    const int* src = ei;
    const int* dst = ei + E_EDGES;

    k_count_cvt<<<SCAT_BLOCKS, 256>>>(dst, W1, Wmu, Wls);
    k_chunk_sum<<<NCHUNKS, CHUNK>>>();
    k_chunk_scan<<<NCHUNKS, CHUNK>>>();
    k_gemm1_scatter<<<GEMM1_BLOCKS + SCAT_BLOCKS, 256>>>(src, dst, x);
    {
        long long total = (long long)N_NODES * 32;
        int blocks = (int)((total + 255) / 256);
        k_agg<1><<<blocks, 256>>>(b1);
        k_agg<2><<<blocks, 256>>>(nullptr);
    }
    k_gemm2<<<N_PAD / 32, 256>>>(bmu, bls, eps, out);
}